// round 11
// baseline (speedup 1.0000x reference)
#include <cuda_runtime.h>
#include <cstdint>

#define N_NODES 100000
#define N_EDGES 1250000
#define FEAT    64
#define NCLS    32
#define CAP     96
#define N_TILES 782     // ceil(N_NODES/128)
#define FGRID   391     // persistent fused grid: 2 tiles/block, single wave

// k-row XOR swizzle of the node-block index (16B granularity)
#define KEY(k)  (((k) >> 2) & 7)

// ---- scratch (no allocations allowed; __device__ globals) ----
__device__ __align__(16) float g_agg[(size_t)N_NODES * FEAT];
__device__ __align__(16) float g_t  [(size_t)N_NODES * NCLS];
__device__ int g_cnt [N_NODES];
__device__ int g_list[(size_t)N_NODES * CAP];

// ---------------------------------------------------------------------------
__global__ void zero_cnt_kernel() {
    int i = blockIdx.x * blockDim.x + threadIdx.x;
    if (i < N_NODES) g_cnt[i] = 0;
}

__global__ void fill_kernel(const int* __restrict__ src,
                            const int* __restrict__ dst) {
    int e = blockIdx.x * blockDim.x + threadIdx.x;
    if (e >= N_EDGES) return;
    int d = __ldg(&dst[e]);
    int pos = atomicAdd(&g_cnt[d], 1);
    if (pos < CAP)
        g_list[(size_t)d * CAP + pos] = __ldg(&src[e]);
}

// ---------------------------------------------------------------------------
// gather layer 1: g_agg[n] = mean over in-neighbors of x[s]   (16 thr/node)
// ---------------------------------------------------------------------------
__global__ void gather1_kernel(const float* __restrict__ x) {
    int t = blockIdx.x * blockDim.x + threadIdx.x;
    if (t >= N_NODES * 16) return;
    int n = t >> 4;
    int c = (t & 15) * 4;

    int cnt = min(g_cnt[n], CAP);
    const int* lst = g_list + (size_t)n * CAP;

    float4 acc = make_float4(0.f, 0.f, 0.f, 0.f);
    int j = 0;
    for (; j + 1 < cnt; j += 2) {
        int s0 = __ldg(&lst[j]);
        int s1 = __ldg(&lst[j + 1]);
        float4 v0 = *reinterpret_cast<const float4*>(x + (size_t)s0 * FEAT + c);
        float4 v1 = *reinterpret_cast<const float4*>(x + (size_t)s1 * FEAT + c);
        acc.x += v0.x + v1.x; acc.y += v0.y + v1.y;
        acc.z += v0.z + v1.z; acc.w += v0.w + v1.w;
    }
    if (j < cnt) {
        int s0 = __ldg(&lst[j]);
        float4 v0 = *reinterpret_cast<const float4*>(x + (size_t)s0 * FEAT + c);
        acc.x += v0.x; acc.y += v0.y; acc.z += v0.z; acc.w += v0.w;
    }
    float invd = 1.0f / fmaxf((float)cnt, 1.0f);
    acc.x *= invd; acc.y *= invd; acc.z *= invd; acc.w *= invd;
    *reinterpret_cast<float4*>(g_agg + (size_t)n * FEAT + c) = acc;
}

// ---------------------------------------------------------------------------
// gather layer 2: out[n] += mean over in-neighbors of g_t[s]  (8 thr/node)
// ---------------------------------------------------------------------------
__global__ void gather2_kernel(float* __restrict__ out) {
    int t = blockIdx.x * blockDim.x + threadIdx.x;
    if (t >= N_NODES * 8) return;
    int n = t >> 3;
    int c = (t & 7) * 4;

    int cnt = min(g_cnt[n], CAP);
    const int* lst = g_list + (size_t)n * CAP;

    float4 acc = make_float4(0.f, 0.f, 0.f, 0.f);
    int j = 0;
    for (; j + 1 < cnt; j += 2) {
        int s0 = __ldg(&lst[j]);
        int s1 = __ldg(&lst[j + 1]);
        float4 v0 = *reinterpret_cast<const float4*>(g_t + (size_t)s0 * NCLS + c);
        float4 v1 = *reinterpret_cast<const float4*>(g_t + (size_t)s1 * NCLS + c);
        acc.x += v0.x + v1.x; acc.y += v0.y + v1.y;
        acc.z += v0.z + v1.z; acc.w += v0.w + v1.w;
    }
    if (j < cnt) {
        int s0 = __ldg(&lst[j]);
        float4 v0 = *reinterpret_cast<const float4*>(g_t + (size_t)s0 * NCLS + c);
        acc.x += v0.x; acc.y += v0.y; acc.z += v0.z; acc.w += v0.w;
    }
    float invd = 1.0f / fmaxf((float)cnt, 1.0f);
    float4* o = reinterpret_cast<float4*>(out + (size_t)n * NCLS + c);
    float4 v = *o;
    v.x += acc.x * invd; v.y += acc.y * invd;
    v.z += acc.z * invd; v.w += acc.w * invd;
    *o = v;
}

// ---------------------------------------------------------------------------
// fused dense, persistent: each block processes 2 tiles of 128 nodes.
//   phase 1 (2 halves): h1 = relu(x@Ws1 + agg@Wn1 + b1), K=64 per half
//   phase 2: [out|g_t] = h1 @ [Ws2|Wn2] (+b2 self), K=64, h1 in smem
// 128 threads, 8x8 thread tile. Full W resident in 16KB -> 6 barriers/tile.
// A-tile: k-major, stride 128, XOR-swizzled node-blocks (conflict-free STS).
// W-tile: [k][half][colgrp][4] (conflict-free inner LDS.128).
// ---------------------------------------------------------------------------
__global__ void __launch_bounds__(128)
fused_dense_kernel(const float* __restrict__ x,
                   const float* __restrict__ Ws1,
                   const float* __restrict__ Wn1,
                   const float* __restrict__ b1v,
                   const float* __restrict__ Ws2,
                   const float* __restrict__ Wn2,
                   const float* __restrict__ b2v,
                   float* __restrict__ out) {
    __shared__ __align__(16) float pool[64 * 128 + 64 * FEAT];  // 49152 B
    float* sW = pool + 64 * 128;

    int tid = threadIdx.x;
    int col = tid & 7;                     // output group (8 outputs)
    int row = tid >> 3;                    // node group (8 nodes)
    int b0 = 2 * row, b1i = 2 * row + 1;
    bool self = col < 4;

    for (int tile = blockIdx.x; tile < N_TILES; tile += FGRID) {
        int nb = tile * 128;

        float acc[8][8];
#pragma unroll
        for (int j = 0; j < 8; j++) {
            float bv = __ldg(&b1v[col * 8 + j]);
#pragma unroll
            for (int i = 0; i < 8; i++) acc[i][j] = bv;
        }

        // ---------------- phase 1: two halves (x@Ws1, agg@Wn1) ----------------
#pragma unroll 1
        for (int half = 0; half < 2; half++) {
            const float* Asrc = half ? g_agg : x;
            const float* Wsrc = half ? Wn1 : Ws1;

            // stage A (64 k-rows, transposed + swizzled), two conflict-free passes
#pragma unroll
            for (int s = 0; s < 2; s++) {
                int koff = s * 32;
#pragma unroll
                for (int r = 0; r < 8; r++) {
                    int fid = tid + r * 128;     // 0..1023
                    int node = fid >> 3;         // 0..127
                    int kq = fid & 7;
                    int n = nb + node;
                    float4 v = (n < N_NODES)
                        ? *reinterpret_cast<const float4*>(Asrc + (size_t)n * FEAT + koff + kq * 4)
                        : make_float4(0.f, 0.f, 0.f, 0.f);
                    int sw = (((node >> 2) ^ kq) << 2) + (node & 3);
                    pool[(koff + kq * 4 + 0) * 128 + sw] = v.x;
                    pool[(koff + kq * 4 + 1) * 128 + sw] = v.y;
                    pool[(koff + kq * 4 + 2) * 128 + sw] = v.z;
                    pool[(koff + kq * 4 + 3) * 128 + sw] = v.w;
                }
            }
            // stage full W (64x64): layout [k][oq&1][oq>>1][4]
#pragma unroll
            for (int r = 0; r < 8; r++) {
                int fid = tid + r * 128;         // 0..1023
                int k = fid >> 4;
                int oq = fid & 15;
                float4 v = *reinterpret_cast<const float4*>(Wsrc + (size_t)k * FEAT + oq * 4);
                *reinterpret_cast<float4*>(&sW[k * FEAT + (oq & 1) * 32 + (oq >> 1) * 4]) = v;
            }
            __syncthreads();

#pragma unroll 8
            for (int k = 0; k < FEAT; k++) {
                float4 a0 = *reinterpret_cast<const float4*>(&pool[k * 128 + ((b0 ^ KEY(k)) << 2)]);
                float4 a1 = *reinterpret_cast<const float4*>(&pool[k * 128 + ((b1i ^ KEY(k)) << 2)]);
                float4 w0 = *reinterpret_cast<const float4*>(&sW[k * FEAT + col * 4]);
                float4 w1 = *reinterpret_cast<const float4*>(&sW[k * FEAT + 32 + col * 4]);
                float av[8] = {a0.x, a0.y, a0.z, a0.w, a1.x, a1.y, a1.z, a1.w};
                float wv[8] = {w0.x, w0.y, w0.z, w0.w, w1.x, w1.y, w1.z, w1.w};
#pragma unroll
                for (int i = 0; i < 8; i++)
#pragma unroll
                    for (int j = 0; j < 8; j++)
                        acc[i][j] += av[i] * wv[j];
            }
            __syncthreads();
        }

        // ---- h1 tile -> smem (relu, k-major, swizzled) ----
#pragma unroll
        for (int j = 0; j < 8; j++) {
            int o = col * 8 + j;               // h1 feature index = phase-2 k
            float4 v0 = make_float4(fmaxf(acc[0][j], 0.f), fmaxf(acc[1][j], 0.f),
                                    fmaxf(acc[2][j], 0.f), fmaxf(acc[3][j], 0.f));
            float4 v1 = make_float4(fmaxf(acc[4][j], 0.f), fmaxf(acc[5][j], 0.f),
                                    fmaxf(acc[6][j], 0.f), fmaxf(acc[7][j], 0.f));
            *reinterpret_cast<float4*>(&pool[o * 128 + ((b0 ^ KEY(o)) << 2)]) = v0;
            *reinterpret_cast<float4*>(&pool[o * 128 + ((b1i ^ KEY(o)) << 2)]) = v1;
        }

        // phase 2 init + stage W2 = [Ws2 | Wn2]
#pragma unroll
        for (int j = 0; j < 8; j++) {
            float bv = self ? __ldg(&b2v[col * 8 + j]) : 0.f;
#pragma unroll
            for (int i = 0; i < 8; i++) acc[i][j] = bv;
        }
#pragma unroll
        for (int r = 0; r < 8; r++) {
            int fid = tid + r * 128;           // 0..1023
            int k = fid >> 4;
            int oq = fid & 15;                 // 0..7 self (Ws2), 8..15 neigh (Wn2)
            float4 v = (oq < 8)
                ? *reinterpret_cast<const float4*>(Ws2 + (size_t)k * NCLS + oq * 4)
                : *reinterpret_cast<const float4*>(Wn2 + (size_t)k * NCLS + (oq - 8) * 4);
            *reinterpret_cast<float4*>(&sW[k * FEAT + (oq & 1) * 32 + (oq >> 1) * 4]) = v;
        }
        __syncthreads();                       // h1 + W2 visible

        // ---------------- phase 2: K = 64 from smem h1 ----------------
#pragma unroll 8
        for (int k = 0; k < FEAT; k++) {
            float4 a0 = *reinterpret_cast<const float4*>(&pool[k * 128 + ((b0 ^ KEY(k)) << 2)]);
            float4 a1 = *reinterpret_cast<const float4*>(&pool[k * 128 + ((b1i ^ KEY(k)) << 2)]);
            float4 w0 = *reinterpret_cast<const float4*>(&sW[k * FEAT + col * 4]);
            float4 w1 = *reinterpret_cast<const float4*>(&sW[k * FEAT + 32 + col * 4]);
            float av[8] = {a0.x, a0.y, a0.z, a0.w, a1.x, a1.y, a1.z, a1.w};
            float wv[8] = {w0.x, w0.y, w0.z, w0.w, w1.x, w1.y, w1.z, w1.w};
#pragma unroll
            for (int i = 0; i < 8; i++)
#pragma unroll
                for (int j = 0; j < 8; j++)
                    acc[i][j] += av[i] * wv[j];
        }

        // ---------------- stores ----------------
#pragma unroll
        for (int i = 0; i < 8; i++) {
            int n = nb + row * 8 + i;
            if (n >= N_NODES) continue;
            float4 v0 = make_float4(acc[i][0], acc[i][1], acc[i][2], acc[i][3]);
            float4 v1 = make_float4(acc[i][4], acc[i][5], acc[i][6], acc[i][7]);
            if (self) {
                float4* op = reinterpret_cast<float4*>(out + (size_t)n * NCLS + col * 8);
                op[0] = v0;
                op[1] = v1;
            } else {
                float4* tp = reinterpret_cast<float4*>(g_t + (size_t)n * NCLS + (col - 4) * 8);
                tp[0] = v0;
                tp[1] = v1;
            }
        }
        __syncthreads();                       // pool reuse safe for next tile
    }
}

// ---------------------------------------------------------------------------
extern "C" void kernel_launch(void* const* d_in, const int* in_sizes, int n_in,
                              void* d_out, int out_size) {
    const float* x   = (const float*)d_in[0];
    const int*   src = (const int*)d_in[1];
    const int*   dst = (const int*)d_in[2];
    const float* Ws1 = (const float*)d_in[3];
    const float* Wn1 = (const float*)d_in[4];
    const float* b1  = (const float*)d_in[5];
    const float* Ws2 = (const float*)d_in[6];
    const float* Wn2 = (const float*)d_in[7];
    const float* b2  = (const float*)d_in[8];
    float* out = (float*)d_out;

    const int T = 256;
    int zc_blocks = (N_NODES + T - 1) / T;
    int fl_blocks = (N_EDGES + T - 1) / T;
    int g1_blocks = (N_NODES * 16 + T - 1) / T;
    int g2_blocks = (N_NODES * 8 + T - 1) / T;

    // build adjacency buckets (dst -> [src...])
    zero_cnt_kernel<<<zc_blocks, T>>>();
    fill_kernel<<<fl_blocks, T>>>(src, dst);

    // layer 1 aggregation
    gather1_kernel<<<g1_blocks, T>>>(x);

    // fused dense: layer1 GEMM + relu + layer2 transform (h1 stays in smem)
    fused_dense_kernel<<<FGRID, 128>>>(x, Ws1, Wn1, b1, Ws2, Wn2, b2, out);

    // layer 2 aggregation (agg(h1@Wn2) == agg-then-transform by linearity)
    gather2_kernel<<<g2_blocks, T>>>(out);
}

// round 12
// speedup vs baseline: 1.0048x; 1.0048x over previous
#include <cuda_runtime.h>
#include <cstdint>

#define N_NODES 100000
#define N_EDGES 1250000
#define FEAT    64
#define NCLS    32
#define CAP     96
#define KC      32      // k-chunk for GEMM staging
#define APAD    132     // tile row stride (floats): 16B-aligned
#define N_TILES 782     // ceil(N_NODES/128)
#define FGRID   391     // persistent fused grid: 2 tiles/block, single wave

// k-row XOR swizzle of the node-block index (16B granularity)
#define KEY(k)  (((k) >> 2) & 7)

// ---- scratch (no allocations allowed; __device__ globals) ----
__device__ __align__(16) float g_agg[(size_t)N_NODES * FEAT];
__device__ __align__(16) float g_t  [(size_t)N_NODES * NCLS];
__device__ int g_cnt [N_NODES];
__device__ int g_list[(size_t)N_NODES * CAP];

// ---------------------------------------------------------------------------
__global__ void zero_cnt_kernel() {
    int i = blockIdx.x * blockDim.x + threadIdx.x;
    if (i < N_NODES) g_cnt[i] = 0;
}

__global__ void fill_kernel(const int* __restrict__ src,
                            const int* __restrict__ dst) {
    int e = blockIdx.x * blockDim.x + threadIdx.x;
    if (e >= N_EDGES) return;
    int d = __ldg(&dst[e]);
    int pos = atomicAdd(&g_cnt[d], 1);
    if (pos < CAP)
        g_list[(size_t)d * CAP + pos] = __ldg(&src[e]);
}

// ---------------------------------------------------------------------------
// gather layer 1: g_agg[n] = mean over in-neighbors of x[s]   (16 thr/node)
// ---------------------------------------------------------------------------
__global__ void gather1_kernel(const float* __restrict__ x) {
    int t = blockIdx.x * blockDim.x + threadIdx.x;
    if (t >= N_NODES * 16) return;
    int n = t >> 4;
    int c = (t & 15) * 4;

    int cnt = min(g_cnt[n], CAP);
    const int* lst = g_list + (size_t)n * CAP;

    float4 acc = make_float4(0.f, 0.f, 0.f, 0.f);
    int j = 0;
    for (; j + 1 < cnt; j += 2) {
        int s0 = __ldg(&lst[j]);
        int s1 = __ldg(&lst[j + 1]);
        float4 v0 = *reinterpret_cast<const float4*>(x + (size_t)s0 * FEAT + c);
        float4 v1 = *reinterpret_cast<const float4*>(x + (size_t)s1 * FEAT + c);
        acc.x += v0.x + v1.x; acc.y += v0.y + v1.y;
        acc.z += v0.z + v1.z; acc.w += v0.w + v1.w;
    }
    if (j < cnt) {
        int s0 = __ldg(&lst[j]);
        float4 v0 = *reinterpret_cast<const float4*>(x + (size_t)s0 * FEAT + c);
        acc.x += v0.x; acc.y += v0.y; acc.z += v0.z; acc.w += v0.w;
    }
    float invd = 1.0f / fmaxf((float)cnt, 1.0f);
    acc.x *= invd; acc.y *= invd; acc.z *= invd; acc.w *= invd;
    *reinterpret_cast<float4*>(g_agg + (size_t)n * FEAT + c) = acc;
}

// ---------------------------------------------------------------------------
// gather layer 2: out[n] += mean over in-neighbors of g_t[s]  (8 thr/node)
// ---------------------------------------------------------------------------
__global__ void gather2_kernel(float* __restrict__ out) {
    int t = blockIdx.x * blockDim.x + threadIdx.x;
    if (t >= N_NODES * 8) return;
    int n = t >> 3;
    int c = (t & 7) * 4;

    int cnt = min(g_cnt[n], CAP);
    const int* lst = g_list + (size_t)n * CAP;

    float4 acc = make_float4(0.f, 0.f, 0.f, 0.f);
    int j = 0;
    for (; j + 1 < cnt; j += 2) {
        int s0 = __ldg(&lst[j]);
        int s1 = __ldg(&lst[j + 1]);
        float4 v0 = *reinterpret_cast<const float4*>(g_t + (size_t)s0 * NCLS + c);
        float4 v1 = *reinterpret_cast<const float4*>(g_t + (size_t)s1 * NCLS + c);
        acc.x += v0.x + v1.x; acc.y += v0.y + v1.y;
        acc.z += v0.z + v1.z; acc.w += v0.w + v1.w;
    }
    if (j < cnt) {
        int s0 = __ldg(&lst[j]);
        float4 v0 = *reinterpret_cast<const float4*>(g_t + (size_t)s0 * NCLS + c);
        acc.x += v0.x; acc.y += v0.y; acc.z += v0.z; acc.w += v0.w;
    }
    float invd = 1.0f / fmaxf((float)cnt, 1.0f);
    float4* o = reinterpret_cast<float4*>(out + (size_t)n * NCLS + c);
    float4 v = *o;
    v.x += acc.x * invd; v.y += acc.y * invd;
    v.z += acc.z * invd; v.w += acc.w * invd;
    *o = v;
}

// ---------------------------------------------------------------------------
// fused dense (R10 body, persistent grid): 2 tiles of 128 nodes per block.
//   phase 1: h1 = relu([x|agg] @ [Ws1;Wn1] + b1)    (K=128, into smem)
//   phase 2: [out|g_t] = h1 @ [Ws2|Wn2] (+b2 self)  (K=64, from smem)
// 128 threads, 8x8 thread tile; KC=32 chunks FULLY unrolled so all
// XOR-swizzled smem addresses are compile-time constants.
// ---------------------------------------------------------------------------
__global__ void __launch_bounds__(128)
fused_dense_kernel(const float* __restrict__ x,
                   const float* __restrict__ Ws1,
                   const float* __restrict__ Wn1,
                   const float* __restrict__ b1v,
                   const float* __restrict__ Ws2,
                   const float* __restrict__ Wn2,
                   const float* __restrict__ b2v,
                   float* __restrict__ out) {
    __shared__ __align__(16) float pool[64 * APAD + KC * FEAT];  // 41984 B
    float* sW = pool + 64 * APAD;

    int tid = threadIdx.x;
    int col = tid & 7;                     // output group (8 outputs)
    int row = tid >> 3;                    // node group (8 nodes: blocks 2row,2row+1)
    int b0 = 2 * row, b1i = 2 * row + 1;
    bool self = col < 4;

    for (int tile = blockIdx.x; tile < N_TILES; tile += FGRID) {
        int nb = tile * 128;

        float acc[8][8];
#pragma unroll
        for (int j = 0; j < 8; j++) {
            float bv = __ldg(&b1v[col * 8 + j]);
#pragma unroll
            for (int i = 0; i < 8; i++) acc[i][j] = bv;
        }

        // ---------------- phase 1: K = 128 over [x | agg] ----------------
#pragma unroll 1
        for (int kg0 = 0; kg0 < 2 * FEAT; kg0 += KC) {
            const float* Asrc = (kg0 < FEAT) ? x : g_agg;
            const float* Wsrc = (kg0 < FEAT) ? Ws1 : Wn1;
            int koff = kg0 & (FEAT - 1);

            // stage A chunk, transposed + swizzled
#pragma unroll
            for (int r = 0; r < 8; r++) {
                int fid = tid + r * 128;       // 0..1023
                int node = fid >> 3;           // 0..127
                int kq = fid & 7;
                int n = nb + node;
                float4 v = (n < N_NODES)
                    ? *reinterpret_cast<const float4*>(Asrc + (size_t)n * FEAT + koff + kq * 4)
                    : make_float4(0.f, 0.f, 0.f, 0.f);
                int sw = (((node >> 2) ^ kq) << 2) + (node & 3);
                pool[(kq * 4 + 0) * APAD + sw] = v.x;
                pool[(kq * 4 + 1) * APAD + sw] = v.y;
                pool[(kq * 4 + 2) * APAD + sw] = v.z;
                pool[(kq * 4 + 3) * APAD + sw] = v.w;
            }
            // stage W chunk: layout [k][oq&1][oq>>1][4]
#pragma unroll
            for (int r = 0; r < 4; r++) {
                int fid = tid + r * 128;       // 0..511
                int k = fid >> 4;
                int oq = fid & 15;
                float4 v = *reinterpret_cast<const float4*>(Wsrc + (size_t)(koff + k) * FEAT + oq * 4);
                *reinterpret_cast<float4*>(&sW[k * FEAT + (oq & 1) * 32 + (oq >> 1) * 4]) = v;
            }
            __syncthreads();

#pragma unroll
            for (int k = 0; k < KC; k++) {
                float4 a0 = *reinterpret_cast<const float4*>(&pool[k * APAD + ((b0 ^ KEY(k)) << 2)]);
                float4 a1 = *reinterpret_cast<const float4*>(&pool[k * APAD + ((b1i ^ KEY(k)) << 2)]);
                float4 w0 = *reinterpret_cast<const float4*>(&sW[k * FEAT + col * 4]);
                float4 w1 = *reinterpret_cast<const float4*>(&sW[k * FEAT + 32 + col * 4]);
                float av[8] = {a0.x, a0.y, a0.z, a0.w, a1.x, a1.y, a1.z, a1.w};
                float wv[8] = {w0.x, w0.y, w0.z, w0.w, w1.x, w1.y, w1.z, w1.w};
#pragma unroll
                for (int i = 0; i < 8; i++)
#pragma unroll
                    for (int j = 0; j < 8; j++)
                        acc[i][j] += av[i] * wv[j];
            }
            __syncthreads();
        }

        // ---- h1 tile -> smem (relu, k-major, swizzled, float4 over nodes) ----
#pragma unroll
        for (int j = 0; j < 8; j++) {
            int o = col * 8 + j;               // h1 feature index = phase-2 k
            float4 v0 = make_float4(fmaxf(acc[0][j], 0.f), fmaxf(acc[1][j], 0.f),
                                    fmaxf(acc[2][j], 0.f), fmaxf(acc[3][j], 0.f));
            float4 v1 = make_float4(fmaxf(acc[4][j], 0.f), fmaxf(acc[5][j], 0.f),
                                    fmaxf(acc[6][j], 0.f), fmaxf(acc[7][j], 0.f));
            *reinterpret_cast<float4*>(&pool[o * APAD + ((b0 ^ KEY(o)) << 2)]) = v0;
            *reinterpret_cast<float4*>(&pool[o * APAD + ((b1i ^ KEY(o)) << 2)]) = v1;
        }

        // ---------------- phase 2 init ----------------
#pragma unroll
        for (int j = 0; j < 8; j++) {
            float bv = self ? __ldg(&b2v[col * 8 + j]) : 0.f;
#pragma unroll
            for (int i = 0; i < 8; i++) acc[i][j] = bv;
        }
        __syncthreads();                       // h1 tile visible to all warps

        // ---------------- phase 2: K = 64 from smem h1 ----------------
#pragma unroll 1
        for (int kc2 = 0; kc2 < FEAT; kc2 += KC) {
#pragma unroll
            for (int r = 0; r < 4; r++) {
                int fid = tid + r * 128;       // 0..511
                int k = fid >> 4;
                int oq = fid & 15;             // 0..7 self (Ws2), 8..15 neigh (Wn2)
                float4 v = (oq < 8)
                    ? *reinterpret_cast<const float4*>(Ws2 + (size_t)(kc2 + k) * NCLS + oq * 4)
                    : *reinterpret_cast<const float4*>(Wn2 + (size_t)(kc2 + k) * NCLS + (oq - 8) * 4);
                *reinterpret_cast<float4*>(&sW[k * FEAT + (oq & 1) * 32 + (oq >> 1) * 4]) = v;
            }
            __syncthreads();

#pragma unroll
            for (int k = 0; k < KC; k++) {
                int kk = kc2 + k;              // kc2 uniform; KEY(kk)=KEY(k)^KEY(kc2) const per iter
                float4 a0 = *reinterpret_cast<const float4*>(&pool[kk * APAD + ((b0 ^ KEY(kk)) << 2)]);
                float4 a1 = *reinterpret_cast<const float4*>(&pool[kk * APAD + ((b1i ^ KEY(kk)) << 2)]);
                float4 w0 = *reinterpret_cast<const float4*>(&sW[k * FEAT + col * 4]);
                float4 w1 = *reinterpret_cast<const float4*>(&sW[k * FEAT + 32 + col * 4]);
                float av[8] = {a0.x, a0.y, a0.z, a0.w, a1.x, a1.y, a1.z, a1.w};
                float wv[8] = {w0.x, w0.y, w0.z, w0.w, w1.x, w1.y, w1.z, w1.w};
#pragma unroll
                for (int i = 0; i < 8; i++)
#pragma unroll
                    for (int j = 0; j < 8; j++)
                        acc[i][j] += av[i] * wv[j];
            }
            __syncthreads();
        }

        // ---------------- stores ----------------
#pragma unroll
        for (int i = 0; i < 8; i++) {
            int n = nb + row * 8 + i;
            if (n >= N_NODES) continue;
            float4 v0 = make_float4(acc[i][0], acc[i][1], acc[i][2], acc[i][3]);
            float4 v1 = make_float4(acc[i][4], acc[i][5], acc[i][6], acc[i][7]);
            if (self) {
                float4* op = reinterpret_cast<float4*>(out + (size_t)n * NCLS + col * 8);
                op[0] = v0;
                op[1] = v1;
            } else {
                float4* tp = reinterpret_cast<float4*>(g_t + (size_t)n * NCLS + (col - 4) * 8);
                tp[0] = v0;
                tp[1] = v1;
            }
        }
        __syncthreads();                       // pool reuse safe for next tile
    }
}

// ---------------------------------------------------------------------------
extern "C" void kernel_launch(void* const* d_in, const int* in_sizes, int n_in,
                              void* d_out, int out_size) {
    const float* x   = (const float*)d_in[0];
    const int*   src = (const int*)d_in[1];
    const int*   dst = (const int*)d_in[2];
    const float* Ws1 = (const float*)d_in[3];
    const float* Wn1 = (const float*)d_in[4];
    const float* b1  = (const float*)d_in[5];
    const float* Ws2 = (const float*)d_in[6];
    const float* Wn2 = (const float*)d_in[7];
    const float* b2  = (const float*)d_in[8];
    float* out = (float*)d_out;

    const int T = 256;
    int zc_blocks = (N_NODES + T - 1) / T;
    int fl_blocks = (N_EDGES + T - 1) / T;
    int g1_blocks = (N_NODES * 16 + T - 1) / T;
    int g2_blocks = (N_NODES * 8 + T - 1) / T;

    // build adjacency buckets (dst -> [src...])
    zero_cnt_kernel<<<zc_blocks, T>>>();
    fill_kernel<<<fl_blocks, T>>>(src, dst);

    // layer 1 aggregation
    gather1_kernel<<<g1_blocks, T>>>(x);

    // fused dense: layer1 GEMM + relu + layer2 transform (h1 stays in smem)
    fused_dense_kernel<<<FGRID, 128>>>(x, Ws1, Wn1, b1, Ws2, Wn2, b2, out);

    // layer 2 aggregation (agg(h1@Wn2) == agg-then-transform by linearity)
    gather2_kernel<<<g2_blocks, T>>>(out);
}

// round 13
// speedup vs baseline: 1.1061x; 1.1008x over previous
#include <cuda_runtime.h>
#include <cstdint>

#define N_NODES 100000
#define N_EDGES 1250000
#define FEAT    64
#define NCLS    32
#define CAP     96
#define KC      32      // k-chunk for GEMM staging
#define APAD    132     // tile row stride (floats): 16B-aligned

// k-row XOR swizzle of the node-block index (16B granularity)
#define KEY(k)  (((k) >> 2) & 7)

typedef unsigned long long ull;

// ---- f32x2 packed helpers (Blackwell FFMA2 via PTX) ----
__device__ __forceinline__ ull pack_dup(float a) {
    ull r; asm("mov.b64 %0, {%1, %1};" : "=l"(r) : "f"(a)); return r;
}
__device__ __forceinline__ ull pack2(float lo, float hi) {
    ull r; asm("mov.b64 %0, {%1, %2};" : "=l"(r) : "f"(lo), "f"(hi)); return r;
}
__device__ __forceinline__ void unpack2(ull v, float& lo, float& hi) {
    asm("mov.b64 {%0, %1}, %2;" : "=f"(lo), "=f"(hi) : "l"(v));
}
__device__ __forceinline__ void ffma2(ull& d, ull a, ull b) {
    asm("fma.rn.f32x2 %0, %1, %2, %0;" : "+l"(d) : "l"(a), "l"(b));
}

// ---- scratch (no allocations allowed; __device__ globals) ----
__device__ __align__(16) float g_agg[(size_t)N_NODES * FEAT];
__device__ __align__(16) float g_t  [(size_t)N_NODES * NCLS];
__device__ int g_cnt [N_NODES];
__device__ int g_list[(size_t)N_NODES * CAP];

// ---------------------------------------------------------------------------
__global__ void zero_cnt_kernel() {
    int i = blockIdx.x * blockDim.x + threadIdx.x;
    if (i < N_NODES) g_cnt[i] = 0;
}

__global__ void fill_kernel(const int* __restrict__ src,
                            const int* __restrict__ dst) {
    int e = blockIdx.x * blockDim.x + threadIdx.x;
    if (e >= N_EDGES) return;
    int d = __ldg(&dst[e]);
    int pos = atomicAdd(&g_cnt[d], 1);
    if (pos < CAP)
        g_list[(size_t)d * CAP + pos] = __ldg(&src[e]);
}

// ---------------------------------------------------------------------------
// gather layer 1: g_agg[n] = mean over in-neighbors of x[s]   (16 thr/node)
// ---------------------------------------------------------------------------
__global__ void gather1_kernel(const float* __restrict__ x) {
    int t = blockIdx.x * blockDim.x + threadIdx.x;
    if (t >= N_NODES * 16) return;
    int n = t >> 4;
    int c = (t & 15) * 4;

    int cnt = min(g_cnt[n], CAP);
    const int* lst = g_list + (size_t)n * CAP;

    float4 acc = make_float4(0.f, 0.f, 0.f, 0.f);
    int j = 0;
    for (; j + 1 < cnt; j += 2) {
        int s0 = __ldg(&lst[j]);
        int s1 = __ldg(&lst[j + 1]);
        float4 v0 = *reinterpret_cast<const float4*>(x + (size_t)s0 * FEAT + c);
        float4 v1 = *reinterpret_cast<const float4*>(x + (size_t)s1 * FEAT + c);
        acc.x += v0.x + v1.x; acc.y += v0.y + v1.y;
        acc.z += v0.z + v1.z; acc.w += v0.w + v1.w;
    }
    if (j < cnt) {
        int s0 = __ldg(&lst[j]);
        float4 v0 = *reinterpret_cast<const float4*>(x + (size_t)s0 * FEAT + c);
        acc.x += v0.x; acc.y += v0.y; acc.z += v0.z; acc.w += v0.w;
    }
    float invd = 1.0f / fmaxf((float)cnt, 1.0f);
    acc.x *= invd; acc.y *= invd; acc.z *= invd; acc.w *= invd;
    *reinterpret_cast<float4*>(g_agg + (size_t)n * FEAT + c) = acc;
}

// ---------------------------------------------------------------------------
// gather layer 2: out[n] += mean over in-neighbors of g_t[s]  (8 thr/node)
// ---------------------------------------------------------------------------
__global__ void gather2_kernel(float* __restrict__ out) {
    int t = blockIdx.x * blockDim.x + threadIdx.x;
    if (t >= N_NODES * 8) return;
    int n = t >> 3;
    int c = (t & 7) * 4;

    int cnt = min(g_cnt[n], CAP);
    const int* lst = g_list + (size_t)n * CAP;

    float4 acc = make_float4(0.f, 0.f, 0.f, 0.f);
    int j = 0;
    for (; j + 1 < cnt; j += 2) {
        int s0 = __ldg(&lst[j]);
        int s1 = __ldg(&lst[j + 1]);
        float4 v0 = *reinterpret_cast<const float4*>(g_t + (size_t)s0 * NCLS + c);
        float4 v1 = *reinterpret_cast<const float4*>(g_t + (size_t)s1 * NCLS + c);
        acc.x += v0.x + v1.x; acc.y += v0.y + v1.y;
        acc.z += v0.z + v1.z; acc.w += v0.w + v1.w;
    }
    if (j < cnt) {
        int s0 = __ldg(&lst[j]);
        float4 v0 = *reinterpret_cast<const float4*>(g_t + (size_t)s0 * NCLS + c);
        acc.x += v0.x; acc.y += v0.y; acc.z += v0.z; acc.w += v0.w;
    }
    float invd = 1.0f / fmaxf((float)cnt, 1.0f);
    float4* o = reinterpret_cast<float4*>(out + (size_t)n * NCLS + c);
    float4 v = *o;
    v.x += acc.x * invd; v.y += acc.y * invd;
    v.z += acc.z * invd; v.w += acc.w * invd;
    *o = v;
}

// ---------------------------------------------------------------------------
// fused dense (R10 structure + FFMA2 inner loops): 1 tile of 128 nodes/block.
//   phase 1: h1 = relu([x|agg] @ [Ws1;Wn1] + b1)    (K=128, into smem)
//   phase 2: [out|g_t] = h1 @ [Ws2|Wn2] (+b2 self)  (K=64, from smem)
// 128 threads, 8x8 thread tile; accumulators are f32x2 pairs (acc2[i][j2] =
// outputs {2j2, 2j2+1} of node i). Per k: 4 LDS.128 + 8 packs + 32 FFMA2.
// ---------------------------------------------------------------------------
__global__ void __launch_bounds__(128)
fused_dense_kernel(const float* __restrict__ x,
                   const float* __restrict__ Ws1,
                   const float* __restrict__ Wn1,
                   const float* __restrict__ b1v,
                   const float* __restrict__ Ws2,
                   const float* __restrict__ Wn2,
                   const float* __restrict__ b2v,
                   float* __restrict__ out) {
    __shared__ __align__(16) float pool[64 * APAD + KC * FEAT];  // 41984 B
    float* sW = pool + 64 * APAD;

    int tid = threadIdx.x;
    int col = tid & 7;                     // output group (8 outputs)
    int row = tid >> 3;                    // node group (8 nodes: blocks 2row,2row+1)
    int b0 = 2 * row, b1i = 2 * row + 1;
    int nb = blockIdx.x * 128;
    bool self = col < 4;

    ull acc2[8][4];
#pragma unroll
    for (int j2 = 0; j2 < 4; j2++) {
        ull bp = pack2(__ldg(&b1v[col * 8 + 2 * j2]), __ldg(&b1v[col * 8 + 2 * j2 + 1]));
#pragma unroll
        for (int i = 0; i < 8; i++) acc2[i][j2] = bp;
    }

    // ---------------- phase 1: K = 128 over [x | agg] ----------------
#pragma unroll 1
    for (int kg0 = 0; kg0 < 2 * FEAT; kg0 += KC) {
        const float* Asrc = (kg0 < FEAT) ? x : g_agg;
        const float* Wsrc = (kg0 < FEAT) ? Ws1 : Wn1;
        int koff = kg0 & (FEAT - 1);

        // stage A chunk, transposed + swizzled
#pragma unroll
        for (int r = 0; r < 8; r++) {
            int fid = tid + r * 128;       // 0..1023
            int node = fid >> 3;           // 0..127
            int kq = fid & 7;
            int n = nb + node;
            float4 v = (n < N_NODES)
                ? *reinterpret_cast<const float4*>(Asrc + (size_t)n * FEAT + koff + kq * 4)
                : make_float4(0.f, 0.f, 0.f, 0.f);
            int sw = (((node >> 2) ^ kq) << 2) + (node & 3);
            pool[(kq * 4 + 0) * APAD + sw] = v.x;
            pool[(kq * 4 + 1) * APAD + sw] = v.y;
            pool[(kq * 4 + 2) * APAD + sw] = v.z;
            pool[(kq * 4 + 3) * APAD + sw] = v.w;
        }
        // stage W chunk: layout [k][oq&1][oq>>1][4]
#pragma unroll
        for (int r = 0; r < 4; r++) {
            int fid = tid + r * 128;       // 0..511
            int k = fid >> 4;
            int oq = fid & 15;
            float4 v = *reinterpret_cast<const float4*>(Wsrc + (size_t)(koff + k) * FEAT + oq * 4);
            *reinterpret_cast<float4*>(&sW[k * FEAT + (oq & 1) * 32 + (oq >> 1) * 4]) = v;
        }
        __syncthreads();

#pragma unroll
        for (int k = 0; k < KC; k++) {
            float4 a0 = *reinterpret_cast<const float4*>(&pool[k * APAD + ((b0 ^ KEY(k)) << 2)]);
            float4 a1 = *reinterpret_cast<const float4*>(&pool[k * APAD + ((b1i ^ KEY(k)) << 2)]);
            ulonglong2 wA = *reinterpret_cast<const ulonglong2*>(&sW[k * FEAT + col * 4]);
            ulonglong2 wB = *reinterpret_cast<const ulonglong2*>(&sW[k * FEAT + 32 + col * 4]);
            float av[8] = {a0.x, a0.y, a0.z, a0.w, a1.x, a1.y, a1.z, a1.w};
#pragma unroll
            for (int i = 0; i < 8; i++) {
                ull ap = pack_dup(av[i]);
                ffma2(acc2[i][0], ap, wA.x);
                ffma2(acc2[i][1], ap, wA.y);
                ffma2(acc2[i][2], ap, wB.x);
                ffma2(acc2[i][3], ap, wB.y);
            }
        }
        __syncthreads();
    }

    // ---- h1 tile -> smem (relu, k-major, swizzled, float4 over nodes) ----
    {
        float accf[8][8];
#pragma unroll
        for (int i = 0; i < 8; i++)
#pragma unroll
            for (int j2 = 0; j2 < 4; j2++)
                unpack2(acc2[i][j2], accf[i][2 * j2], accf[i][2 * j2 + 1]);
#pragma unroll
        for (int j = 0; j < 8; j++) {
            int o = col * 8 + j;               // h1 feature index = phase-2 k
            float4 v0 = make_float4(fmaxf(accf[0][j], 0.f), fmaxf(accf[1][j], 0.f),
                                    fmaxf(accf[2][j], 0.f), fmaxf(accf[3][j], 0.f));
            float4 v1 = make_float4(fmaxf(accf[4][j], 0.f), fmaxf(accf[5][j], 0.f),
                                    fmaxf(accf[6][j], 0.f), fmaxf(accf[7][j], 0.f));
            *reinterpret_cast<float4*>(&pool[o * APAD + ((b0 ^ KEY(o)) << 2)]) = v0;
            *reinterpret_cast<float4*>(&pool[o * APAD + ((b1i ^ KEY(o)) << 2)]) = v1;
        }
    }

    // ---------------- phase 2 init ----------------
#pragma unroll
    for (int j2 = 0; j2 < 4; j2++) {
        ull bp = self ? pack2(__ldg(&b2v[col * 8 + 2 * j2]), __ldg(&b2v[col * 8 + 2 * j2 + 1]))
                      : 0ull;
#pragma unroll
        for (int i = 0; i < 8; i++) acc2[i][j2] = bp;
    }
    __syncthreads();                       // h1 tile visible to all warps

    // ---------------- phase 2: K = 64 from smem h1 ----------------
#pragma unroll 1
    for (int kc2 = 0; kc2 < FEAT; kc2 += KC) {
#pragma unroll
        for (int r = 0; r < 4; r++) {
            int fid = tid + r * 128;       // 0..511
            int k = fid >> 4;
            int oq = fid & 15;             // 0..7 self (Ws2), 8..15 neigh (Wn2)
            float4 v = (oq < 8)
                ? *reinterpret_cast<const float4*>(Ws2 + (size_t)(kc2 + k) * NCLS + oq * 4)
                : *reinterpret_cast<const float4*>(Wn2 + (size_t)(kc2 + k) * NCLS + (oq - 8) * 4);
            *reinterpret_cast<float4*>(&sW[k * FEAT + (oq & 1) * 32 + (oq >> 1) * 4]) = v;
        }
        __syncthreads();

#pragma unroll
        for (int k = 0; k < KC; k++) {
            int kk = kc2 + k;
            float4 a0 = *reinterpret_cast<const float4*>(&pool[kk * APAD + ((b0 ^ KEY(kk)) << 2)]);
            float4 a1 = *reinterpret_cast<const float4*>(&pool[kk * APAD + ((b1i ^ KEY(kk)) << 2)]);
            ulonglong2 wA = *reinterpret_cast<const ulonglong2*>(&sW[k * FEAT + col * 4]);
            ulonglong2 wB = *reinterpret_cast<const ulonglong2*>(&sW[k * FEAT + 32 + col * 4]);
            float av[8] = {a0.x, a0.y, a0.z, a0.w, a1.x, a1.y, a1.z, a1.w};
#pragma unroll
            for (int i = 0; i < 8; i++) {
                ull ap = pack_dup(av[i]);
                ffma2(acc2[i][0], ap, wA.x);
                ffma2(acc2[i][1], ap, wA.y);
                ffma2(acc2[i][2], ap, wB.x);
                ffma2(acc2[i][3], ap, wB.y);
            }
        }
        __syncthreads();
    }

    // ---------------- stores ----------------
    {
        float accf[8][8];
#pragma unroll
        for (int i = 0; i < 8; i++)
#pragma unroll
            for (int j2 = 0; j2 < 4; j2++)
                unpack2(acc2[i][j2], accf[i][2 * j2], accf[i][2 * j2 + 1]);
#pragma unroll
        for (int i = 0; i < 8; i++) {
            int n = nb + row * 8 + i;
            if (n >= N_NODES) continue;
            float4 v0 = make_float4(accf[i][0], accf[i][1], accf[i][2], accf[i][3]);
            float4 v1 = make_float4(accf[i][4], accf[i][5], accf[i][6], accf[i][7]);
            if (self) {
                float4* op = reinterpret_cast<float4*>(out + (size_t)n * NCLS + col * 8);
                op[0] = v0;
                op[1] = v1;
            } else {
                float4* tp = reinterpret_cast<float4*>(g_t + (size_t)n * NCLS + (col - 4) * 8);
                tp[0] = v0;
                tp[1] = v1;
            }
        }
    }
}

// ---------------------------------------------------------------------------
extern "C" void kernel_launch(void* const* d_in, const int* in_sizes, int n_in,
                              void* d_out, int out_size) {
    const float* x   = (const float*)d_in[0];
    const int*   src = (const int*)d_in[1];
    const int*   dst = (const int*)d_in[2];
    const float* Ws1 = (const float*)d_in[3];
    const float* Wn1 = (const float*)d_in[4];
    const float* b1  = (const float*)d_in[5];
    const float* Ws2 = (const float*)d_in[6];
    const float* Wn2 = (const float*)d_in[7];
    const float* b2  = (const float*)d_in[8];
    float* out = (float*)d_out;

    const int T = 256;
    int zc_blocks = (N_NODES + T - 1) / T;
    int fl_blocks = (N_EDGES + T - 1) / T;
    int g1_blocks = (N_NODES * 16 + T - 1) / T;
    int g2_blocks = (N_NODES * 8 + T - 1) / T;
    int dn_blocks = (N_NODES + 127) / 128;

    // build adjacency buckets (dst -> [src...])
    zero_cnt_kernel<<<zc_blocks, T>>>();
    fill_kernel<<<fl_blocks, T>>>(src, dst);

    // layer 1 aggregation
    gather1_kernel<<<g1_blocks, T>>>(x);

    // fused dense: layer1 GEMM + relu + layer2 transform (h1 stays in smem)
    fused_dense_kernel<<<dn_blocks, 128>>>(x, Ws1, Wn1, b1, Ws2, Wn2, b2, out);

    // layer 2 aggregation (agg(h1@Wn2) == agg-then-transform by linearity)
    gather2_kernel<<<g2_blocks, T>>>(out);
}

// round 14
// speedup vs baseline: 1.1122x; 1.0056x over previous
#include <cuda_runtime.h>
#include <cstdint>

#define N_NODES 100000
#define N_EDGES 1250000
#define FEAT    64
#define NCLS    32
#define CAP     96
#define KC      32

// k-row XOR swizzle of the node-block index (16B granularity)
#define KEY(k)  (((k) >> 2) & 7)

typedef unsigned long long ull;

// ---- f32x2 packed helpers (Blackwell FFMA2 via PTX) ----
__device__ __forceinline__ ull pack_dup(float a) {
    ull r; asm("mov.b64 %0, {%1, %1};" : "=l"(r) : "f"(a)); return r;
}
__device__ __forceinline__ ull pack2(float lo, float hi) {
    ull r; asm("mov.b64 %0, {%1, %2};" : "=l"(r) : "f"(lo), "f"(hi)); return r;
}
__device__ __forceinline__ void unpack2(ull v, float& lo, float& hi) {
    asm("mov.b64 {%0, %1}, %2;" : "=f"(lo), "=f"(hi) : "l"(v));
}
__device__ __forceinline__ void ffma2(ull& d, ull a, ull b) {
    asm("fma.rn.f32x2 %0, %1, %2, %0;" : "+l"(d) : "l"(a), "l"(b));
}

// ---- scratch (no allocations allowed; __device__ globals) ----
__device__ __align__(16) float g_agg[(size_t)N_NODES * FEAT];
__device__ __align__(16) float g_t  [(size_t)N_NODES * NCLS];
__device__ int g_cnt [N_NODES];
__device__ int g_list[(size_t)N_NODES * CAP];

// ---------------------------------------------------------------------------
__global__ void zero_cnt_kernel() {
    int i = blockIdx.x * blockDim.x + threadIdx.x;
    if (i < N_NODES) g_cnt[i] = 0;
}

__global__ void fill_kernel(const int* __restrict__ src,
                            const int* __restrict__ dst) {
    int e = blockIdx.x * blockDim.x + threadIdx.x;
    if (e >= N_EDGES) return;
    int d = __ldg(&dst[e]);
    int pos = atomicAdd(&g_cnt[d], 1);
    if (pos < CAP)
        g_list[(size_t)d * CAP + pos] = __ldg(&src[e]);
}

// ---------------------------------------------------------------------------
// gather layer 1: g_agg[n] = mean over in-neighbors of x[s]   (16 thr/node)
// ---------------------------------------------------------------------------
__global__ void gather1_kernel(const float* __restrict__ x) {
    int t = blockIdx.x * blockDim.x + threadIdx.x;
    if (t >= N_NODES * 16) return;
    int n = t >> 4;
    int c = (t & 15) * 4;

    int cnt = min(g_cnt[n], CAP);
    const int* lst = g_list + (size_t)n * CAP;

    float4 acc = make_float4(0.f, 0.f, 0.f, 0.f);
    int j = 0;
    for (; j + 1 < cnt; j += 2) {
        int s0 = __ldg(&lst[j]);
        int s1 = __ldg(&lst[j + 1]);
        float4 v0 = *reinterpret_cast<const float4*>(x + (size_t)s0 * FEAT + c);
        float4 v1 = *reinterpret_cast<const float4*>(x + (size_t)s1 * FEAT + c);
        acc.x += v0.x + v1.x; acc.y += v0.y + v1.y;
        acc.z += v0.z + v1.z; acc.w += v0.w + v1.w;
    }
    if (j < cnt) {
        int s0 = __ldg(&lst[j]);
        float4 v0 = *reinterpret_cast<const float4*>(x + (size_t)s0 * FEAT + c);
        acc.x += v0.x; acc.y += v0.y; acc.z += v0.z; acc.w += v0.w;
    }
    float invd = 1.0f / fmaxf((float)cnt, 1.0f);
    acc.x *= invd; acc.y *= invd; acc.z *= invd; acc.w *= invd;
    *reinterpret_cast<float4*>(g_agg + (size_t)n * FEAT + c) = acc;
}

// ---------------------------------------------------------------------------
// gather layer 2: out[n] += mean over in-neighbors of g_t[s]  (8 thr/node)
// ---------------------------------------------------------------------------
__global__ void gather2_kernel(float* __restrict__ out) {
    int t = blockIdx.x * blockDim.x + threadIdx.x;
    if (t >= N_NODES * 8) return;
    int n = t >> 3;
    int c = (t & 7) * 4;

    int cnt = min(g_cnt[n], CAP);
    const int* lst = g_list + (size_t)n * CAP;

    float4 acc = make_float4(0.f, 0.f, 0.f, 0.f);
    int j = 0;
    for (; j + 1 < cnt; j += 2) {
        int s0 = __ldg(&lst[j]);
        int s1 = __ldg(&lst[j + 1]);
        float4 v0 = *reinterpret_cast<const float4*>(g_t + (size_t)s0 * NCLS + c);
        float4 v1 = *reinterpret_cast<const float4*>(g_t + (size_t)s1 * NCLS + c);
        acc.x += v0.x + v1.x; acc.y += v0.y + v1.y;
        acc.z += v0.z + v1.z; acc.w += v0.w + v1.w;
    }
    if (j < cnt) {
        int s0 = __ldg(&lst[j]);
        float4 v0 = *reinterpret_cast<const float4*>(g_t + (size_t)s0 * NCLS + c);
        acc.x += v0.x; acc.y += v0.y; acc.z += v0.z; acc.w += v0.w;
    }
    float invd = 1.0f / fmaxf((float)cnt, 1.0f);
    float4* o = reinterpret_cast<float4*>(out + (size_t)n * NCLS + c);
    float4 v = *o;
    v.x += acc.x * invd; v.y += acc.y * invd;
    v.z += acc.z * invd; v.w += acc.w * invd;
    *o = v;
}

// ---------------------------------------------------------------------------
// fused dense, double-buffered: 1 tile of 128 nodes per block, 128 threads.
//   phase 1: h1 = relu([x|agg] @ [Ws1;Wn1] + b1)    (K=128, 4 chunks, ping-pong)
//   phase 2: [out|g_t] = h1 @ [Ws2|Wn2] (+b2 self)  (K=64, both W chunks staged)
// 8x8 FFMA2 thread tile. One barrier per phase-1 chunk; LDG prefetch overlaps
// compute. pool rows 0-31 / 32-63 = A ping-pong (phase 1) = h1 (phase 2).
// ---------------------------------------------------------------------------
__global__ void __launch_bounds__(128)
fused_dense_kernel(const float* __restrict__ x,
                   const float* __restrict__ Ws1,
                   const float* __restrict__ Wn1,
                   const float* __restrict__ b1v,
                   const float* __restrict__ Ws2,
                   const float* __restrict__ Wn2,
                   const float* __restrict__ b2v,
                   float* __restrict__ out) {
    __shared__ __align__(16) float pool[64 * 128];    // 32768 B
    __shared__ __align__(16) float sWb[2][KC * FEAT]; // 16384 B  (total 48 KB)

    int tid = threadIdx.x;
    int col = tid & 7;                     // output group (8 outputs)
    int row = tid >> 3;                    // node group (8 nodes: blocks 2row,2row+1)
    int b0 = 2 * row, b1i = 2 * row + 1;
    int nb = blockIdx.x * 128;
    bool self = col < 4;

    ull acc2[8][4];
#pragma unroll
    for (int j2 = 0; j2 < 4; j2++) {
        ull bp = pack2(__ldg(&b1v[col * 8 + 2 * j2]), __ldg(&b1v[col * 8 + 2 * j2 + 1]));
#pragma unroll
        for (int i = 0; i < 8; i++) acc2[i][j2] = bp;
    }

    float4 Areg[8], Wreg[4];

    // ---- prefetch chunk 0 (x, koff 0; Ws1 rows 0..31) ----
#pragma unroll
    for (int r = 0; r < 8; r++) {
        int fid = tid + r * 128;
        int node = fid >> 3, kq = fid & 7;
        int n = nb + node;
        Areg[r] = (n < N_NODES)
            ? *reinterpret_cast<const float4*>(x + (size_t)n * FEAT + kq * 4)
            : make_float4(0.f, 0.f, 0.f, 0.f);
    }
#pragma unroll
    for (int r = 0; r < 4; r++) {
        int fid = tid + r * 128;
        int k = fid >> 4, oq = fid & 15;
        Wreg[r] = *reinterpret_cast<const float4*>(Ws1 + (size_t)k * FEAT + oq * 4);
    }

    // ---------------- phase 1: 4 chunks, 1 barrier each ----------------
#pragma unroll 1
    for (int c = 0; c < 4; c++) {
        int bsel = c & 1;
        float* Abuf = pool + bsel * (KC * 128);
        float* sW = sWb[bsel];

        // store staged regs -> smem (other buffer than chunk c-1's readers)
#pragma unroll
        for (int r = 0; r < 8; r++) {
            int fid = tid + r * 128;
            int node = fid >> 3, kq = fid & 7;
            int sw = (((node >> 2) ^ kq) << 2) + (node & 3);
            Abuf[(kq * 4 + 0) * 128 + sw] = Areg[r].x;
            Abuf[(kq * 4 + 1) * 128 + sw] = Areg[r].y;
            Abuf[(kq * 4 + 2) * 128 + sw] = Areg[r].z;
            Abuf[(kq * 4 + 3) * 128 + sw] = Areg[r].w;
        }
#pragma unroll
        for (int r = 0; r < 4; r++) {
            int fid = tid + r * 128;
            int k = fid >> 4, oq = fid & 15;
            *reinterpret_cast<float4*>(&sW[k * FEAT + (oq & 1) * 32 + (oq >> 1) * 4]) = Wreg[r];
        }
        __syncthreads();

        // prefetch chunk c+1 (overlaps with compute below)
        if (c < 3) {
            const float* Asrc = (c + 1 < 2) ? x : g_agg;
            const float* Wsrc = (c + 1 < 2) ? Ws1 : Wn1;
            int koff = ((c + 1) & 1) * KC;
#pragma unroll
            for (int r = 0; r < 8; r++) {
                int fid = tid + r * 128;
                int node = fid >> 3, kq = fid & 7;
                int n = nb + node;
                Areg[r] = (n < N_NODES)
                    ? *reinterpret_cast<const float4*>(Asrc + (size_t)n * FEAT + koff + kq * 4)
                    : make_float4(0.f, 0.f, 0.f, 0.f);
            }
#pragma unroll
            for (int r = 0; r < 4; r++) {
                int fid = tid + r * 128;
                int k = fid >> 4, oq = fid & 15;
                Wreg[r] = *reinterpret_cast<const float4*>(Wsrc + (size_t)(koff + k) * FEAT + oq * 4);
            }
        }

        // compute chunk c
#pragma unroll
        for (int k = 0; k < KC; k++) {
            float4 a0 = *reinterpret_cast<const float4*>(&Abuf[k * 128 + ((b0 ^ KEY(k)) << 2)]);
            float4 a1 = *reinterpret_cast<const float4*>(&Abuf[k * 128 + ((b1i ^ KEY(k)) << 2)]);
            ulonglong2 wA = *reinterpret_cast<const ulonglong2*>(&sW[k * FEAT + col * 4]);
            ulonglong2 wB = *reinterpret_cast<const ulonglong2*>(&sW[k * FEAT + 32 + col * 4]);
            float av[8] = {a0.x, a0.y, a0.z, a0.w, a1.x, a1.y, a1.z, a1.w};
#pragma unroll
            for (int i = 0; i < 8; i++) {
                ull ap = pack_dup(av[i]);
                ffma2(acc2[i][0], ap, wA.x);
                ffma2(acc2[i][1], ap, wA.y);
                ffma2(acc2[i][2], ap, wB.x);
                ffma2(acc2[i][3], ap, wB.y);
            }
        }
    }
    __syncthreads();                       // all chunk-3 reads done before h1 overwrite

    // ---- h1 tile -> smem (relu, k-major, swizzled); stage BOTH W2 chunks ----
    {
        float accf[8][8];
#pragma unroll
        for (int i = 0; i < 8; i++)
#pragma unroll
            for (int j2 = 0; j2 < 4; j2++)
                unpack2(acc2[i][j2], accf[i][2 * j2], accf[i][2 * j2 + 1]);
#pragma unroll
        for (int j = 0; j < 8; j++) {
            int o = col * 8 + j;               // h1 feature index = phase-2 k
            float4 v0 = make_float4(fmaxf(accf[0][j], 0.f), fmaxf(accf[1][j], 0.f),
                                    fmaxf(accf[2][j], 0.f), fmaxf(accf[3][j], 0.f));
            float4 v1 = make_float4(fmaxf(accf[4][j], 0.f), fmaxf(accf[5][j], 0.f),
                                    fmaxf(accf[6][j], 0.f), fmaxf(accf[7][j], 0.f));
            *reinterpret_cast<float4*>(&pool[o * 128 + ((b0 ^ KEY(o)) << 2)]) = v0;
            *reinterpret_cast<float4*>(&pool[o * 128 + ((b1i ^ KEY(o)) << 2)]) = v1;
        }
    }
#pragma unroll
    for (int r = 0; r < 8; r++) {
        int fid = tid + r * 128;               // 0..1023
        int cc = r >> 2;                       // W2 chunk 0 / 1
        int k = (fid >> 4) & 31;
        int oq = fid & 15;                     // 0..7 self (Ws2), 8..15 neigh (Wn2)
        float4 v = (oq < 8)
            ? *reinterpret_cast<const float4*>(Ws2 + (size_t)(cc * KC + k) * NCLS + oq * 4)
            : *reinterpret_cast<const float4*>(Wn2 + (size_t)(cc * KC + k) * NCLS + (oq - 8) * 4);
        *reinterpret_cast<float4*>(&sWb[cc][k * FEAT + (oq & 1) * 32 + (oq >> 1) * 4]) = v;
    }

    // phase 2 accumulator init
#pragma unroll
    for (int j2 = 0; j2 < 4; j2++) {
        ull bp = self ? pack2(__ldg(&b2v[col * 8 + 2 * j2]), __ldg(&b2v[col * 8 + 2 * j2 + 1]))
                      : 0ull;
#pragma unroll
        for (int i = 0; i < 8; i++) acc2[i][j2] = bp;
    }
    __syncthreads();                       // h1 + both W2 chunks visible

    // ---------------- phase 2: K = 64, no intermediate barriers ----------------
#pragma unroll 1
    for (int c2 = 0; c2 < 2; c2++) {
        const float* Abuf = pool + c2 * (KC * 128);
        const float* sW = sWb[c2];
#pragma unroll
        for (int k = 0; k < KC; k++) {     // KEY(c2*32+k) == KEY(k)
            float4 a0 = *reinterpret_cast<const float4*>(&Abuf[k * 128 + ((b0 ^ KEY(k)) << 2)]);
            float4 a1 = *reinterpret_cast<const float4*>(&Abuf[k * 128 + ((b1i ^ KEY(k)) << 2)]);
            ulonglong2 wA = *reinterpret_cast<const ulonglong2*>(&sW[k * FEAT + col * 4]);
            ulonglong2 wB = *reinterpret_cast<const ulonglong2*>(&sW[k * FEAT + 32 + col * 4]);
            float av[8] = {a0.x, a0.y, a0.z, a0.w, a1.x, a1.y, a1.z, a1.w};
#pragma unroll
            for (int i = 0; i < 8; i++) {
                ull ap = pack_dup(av[i]);
                ffma2(acc2[i][0], ap, wA.x);
                ffma2(acc2[i][1], ap, wA.y);
                ffma2(acc2[i][2], ap, wB.x);
                ffma2(acc2[i][3], ap, wB.y);
            }
        }
    }

    // ---------------- stores ----------------
    {
        float accf[8][8];
#pragma unroll
        for (int i = 0; i < 8; i++)
#pragma unroll
            for (int j2 = 0; j2 < 4; j2++)
                unpack2(acc2[i][j2], accf[i][2 * j2], accf[i][2 * j2 + 1]);
#pragma unroll
        for (int i = 0; i < 8; i++) {
            int n = nb + row * 8 + i;
            if (n >= N_NODES) continue;
            float4 v0 = make_float4(accf[i][0], accf[i][1], accf[i][2], accf[i][3]);
            float4 v1 = make_float4(accf[i][4], accf[i][5], accf[i][6], accf[i][7]);
            if (self) {
                float4* op = reinterpret_cast<float4*>(out + (size_t)n * NCLS + col * 8);
                op[0] = v0;
                op[1] = v1;
            } else {
                float4* tp = reinterpret_cast<float4*>(g_t + (size_t)n * NCLS + (col - 4) * 8);
                tp[0] = v0;
                tp[1] = v1;
            }
        }
    }
}

// ---------------------------------------------------------------------------
extern "C" void kernel_launch(void* const* d_in, const int* in_sizes, int n_in,
                              void* d_out, int out_size) {
    const float* x   = (const float*)d_in[0];
    const int*   src = (const int*)d_in[1];
    const int*   dst = (const int*)d_in[2];
    const float* Ws1 = (const float*)d_in[3];
    const float* Wn1 = (const float*)d_in[4];
    const float* b1  = (const float*)d_in[5];
    const float* Ws2 = (const float*)d_in[6];
    const float* Wn2 = (const float*)d_in[7];
    const float* b2  = (const float*)d_in[8];
    float* out = (float*)d_out;

    const int T = 256;
    int zc_blocks = (N_NODES + T - 1) / T;
    int fl_blocks = (N_EDGES + T - 1) / T;
    int g1_blocks = (N_NODES * 16 + T - 1) / T;
    int g2_blocks = (N_NODES * 8 + T - 1) / T;
    int dn_blocks = (N_NODES + 127) / 128;

    // build adjacency buckets (dst -> [src...])
    zero_cnt_kernel<<<zc_blocks, T>>>();
    fill_kernel<<<fl_blocks, T>>>(src, dst);

    // layer 1 aggregation
    gather1_kernel<<<g1_blocks, T>>>(x);

    // fused dense: layer1 GEMM + relu + layer2 transform (h1 stays in smem)
    fused_dense_kernel<<<dn_blocks, 128>>>(x, Ws1, Wn1, b1, Ws2, Wn2, b2, out);

    // layer 2 aggregation (agg(h1@Wn2) == agg-then-transform by linearity)
    gather2_kernel<<<g2_blocks, T>>>(out);
}